// round 12
// baseline (speedup 1.0000x reference)
#include <cuda_runtime.h>
#include <cuda_fp16.h>
#include <cstdint>

// out[n,R,C,co] = active[n,R/14,C/14] * (bias[co] + sum_{dy,dx,ci} x[n,R+dy,C+dx,ci]*k[dy,dx,ci,co])
// valid 3x3 conv 506x506 -> 504x504, gated per 14x14 tile by mask-block max > 0.5
//
// mma.sync fp16 single-product. Persistent CTAs, 2 CTAs/SM, 256 thr, tile 16x32.
// This round: coalesced staging LDG (oct-inner: 8 lanes = one pixel's 128B) and
// smem-transposed epilogue (conflict-free, fully coalesced STG.128).

#define N_IMG 8
#define H_IN  506
#define W_IN  506
#define H_OUT 504
#define W_OUT 504
#define NBH   36
#define NBW   36

#define RT_CNT 32                     // 16-row tiles (rows 496.. guarded)
#define CT_CNT 16                     // 32-col tiles (cols 480.. guarded)
#define TPI    (RT_CNT * CT_CNT)      // 512
#define N_TILES (N_IMG * TPI)         // 4096
#define GRID_CONV 296

#define THREADS 256

#define XROWP 35                      // pixel-column pitch (odd 16B pitch)
#define PIXB  80                      // 64B fp16 ci0-31 + 16 pad
#define XS_BYTES (18 * XROWP * PIXB)  // 50400
#define WROWB 80                      // 64B fp16 ci + 16 pad
#define WS_BYTES (9 * 32 * WROWB)     // 23040
#define EPIB  2560                    // per-warp epilogue buffer: 16 rows x 160B
#define SMEM_BYTES (XS_BYTES + WS_BYTES + 8 * EPIB)   // 93920 -> 2 CTAs/SM

__device__ float g_active[N_IMG * NBH * NBW];

// ------------------------- helpers ------------------------------------------
__device__ __forceinline__ uint32_t smem_u32(const void* p) {
    uint32_t a;
    asm("{ .reg .u64 t; cvta.to.shared.u64 t, %1; cvt.u32.u64 %0, t; }"
        : "=r"(a) : "l"(p));
    return a;
}
__device__ __forceinline__ void sts64(uint32_t a, uint64_t v) {
    asm volatile("st.shared.b64 [%0], %1;" :: "r"(a), "l"(v) : "memory");
}
__device__ __forceinline__ void lds128(uint32_t a, float4& v) {
    asm volatile("ld.shared.v4.f32 {%0,%1,%2,%3}, [%4];"
                 : "=f"(v.x), "=f"(v.y), "=f"(v.z), "=f"(v.w) : "r"(a));
}
__device__ __forceinline__ void ldsm4(uint32_t* r, uint32_t addr) {
    asm volatile("ldmatrix.sync.aligned.m8n8.x4.shared.b16 {%0,%1,%2,%3}, [%4];"
                 : "=r"(r[0]), "=r"(r[1]), "=r"(r[2]), "=r"(r[3]) : "r"(addr));
}
__device__ __forceinline__ void mma4(float* d, const uint32_t* a, const uint32_t* b) {
    asm volatile(
        "mma.sync.aligned.m16n8k16.row.col.f32.f16.f16.f32 "
        "{%0,%1,%2,%3},{%4,%5,%6,%7},{%8,%9},{%0,%1,%2,%3};"
        : "+f"(d[0]), "+f"(d[1]), "+f"(d[2]), "+f"(d[3])
        : "r"(a[0]), "r"(a[1]), "r"(a[2]), "r"(a[3]), "r"(b[0]), "r"(b[1]));
}

// ---------------- kernel 1: mask block max -> active flag -------------------
__global__ void __launch_bounds__(256) mask_kernel(const float* __restrict__ mask) {
    __shared__ float red[256];
    int b = blockIdx.x;
    int n   = b / (NBH * NBW);
    int rem = b % (NBH * NBW);
    int bi = rem / NBW, bj = rem % NBW;
    int tid = threadIdx.x;
    int rr = tid >> 4, cc = tid & 15;
    red[tid] = mask[(n * H_IN + bi * 14 + rr) * W_IN + bj * 14 + cc];
    __syncthreads();
    #pragma unroll
    for (int s = 128; s > 0; s >>= 1) {
        if (tid < s) red[tid] = fmaxf(red[tid], red[tid + s]);
        __syncthreads();
    }
    if (tid == 0) g_active[b] = (red[0] > 0.5f) ? 1.0f : 0.0f;
}

// ---------------- kernel 2: persistent conv via mma.sync fp16 ---------------
__global__ void __launch_bounds__(THREADS, 2) conv_mma_kernel(
    const float* __restrict__ x,
    const float* __restrict__ kern,
    const float* __restrict__ bias,
    float* __restrict__ out)
{
    extern __shared__ char smem[];
    const uint32_t xs = smem_u32(smem);
    const uint32_t ws = xs + XS_BYTES;
    const uint32_t es = ws + WS_BYTES;
    const int tid = threadIdx.x;
    const int wid = tid >> 5;
    const int lid = tid & 31;

    // ---- stage weights once: kern[tap][ci][co] -> ws[tap][co][ci fp16] ----
    for (int j = tid; j < 2304; j += THREADS) {
        int ciq = j & 7;
        int co  = (j >> 3) & 31;
        int tap = j >> 8;
        int ci  = ciq * 4;
        const float* kp = kern + (tap * 32 + ci) * 32 + co;
        __half2 p0 = __floats2half2_rn(kp[0],  kp[32]);
        __half2 p1 = __floats2half2_rn(kp[64], kp[96]);
        uint64_t v = (uint64_t)(*reinterpret_cast<uint32_t*>(&p0))
                   | ((uint64_t)(*reinterpret_cast<uint32_t*>(&p1)) << 32);
        sts64(ws + (uint32_t)((tap * 32 + co) * WROWB + ciq * 8), v);
    }

    // per-lane ldmatrix base addresses
    const int cw = wid * 4;
    const int irl = (lid & 7) + 8 * ((lid >> 3) & 1);
    const uint32_t baseA = xs + (uint32_t)
        ((irl * XROWP + cw) * PIXB + ((lid >> 4) & 1) * 16);
    const uint32_t baseB = ws + (uint32_t)
        ((((lid & 7) + ((lid >> 4) << 3)) * WROWB) + ((lid >> 3) & 1) * 16);

    // epilogue lane constants
    const int n2 = (lid & 3) * 2;
    const int r0 = lid >> 2;
    const uint32_t eb = es + (uint32_t)(wid * EPIB);
    float2 bv[4];
    #pragma unroll
    for (int nb = 0; nb < 4; nb++)
        bv[nb] = *(const float2*)(bias + nb * 8 + n2);

    for (int t = blockIdx.x; t < N_TILES; t += GRID_CONV) {
        const int n   = t / TPI;
        const int rem = t % TPI;
        const int R0 = (rem >> 4) * 16;
        const int C0 = (rem & 15) * 32;

        __syncthreads();   // previous iteration's readers done before overwrite

        // ---- stage x: 18 rows x 34 cols x 32 ci fp16 (oct-INNER: coalesced) ----
        for (int j = tid; j < 18 * 34 * 8; j += THREADS) {
            int oct = j & 7;                   // 4-ci group (8 lanes = 128B pixel)
            int p   = j >> 3;
            int ir = p / 34, ic = p - ir * 34;
            int gr = R0 + ir; if (gr > H_IN - 1) gr = H_IN - 1;
            int gc = C0 + ic; if (gc > W_IN - 1) gc = W_IN - 1;
            float4 v = *(const float4*)
                (x + (((size_t)n * H_IN + gr) * W_IN + gc) * 32 + oct * 4);
            __half2 h0 = __floats2half2_rn(v.x, v.y);
            __half2 h1 = __floats2half2_rn(v.z, v.w);
            uint64_t pk = (uint64_t)(*reinterpret_cast<uint32_t*>(&h0))
                        | ((uint64_t)(*reinterpret_cast<uint32_t*>(&h1)) << 32);
            sts64(xs + (uint32_t)((ir * XROWP + ic) * PIXB + oct * 8), pk);
        }
        __syncthreads();

        // ---- main loop: dy x h, A-frags shared across dx, single product ----
        float d[4][4][4];
        #pragma unroll
        for (int f = 0; f < 4; f++)
            #pragma unroll
            for (int nb = 0; nb < 4; nb++)
                #pragma unroll
                for (int e = 0; e < 4; e++) d[f][nb][e] = 0.0f;

        #pragma unroll 1
        for (int dy = 0; dy < 3; dy++) {
            #pragma unroll
            for (int h = 0; h < 2; h++) {
                uint32_t A[24], B[8];
                const uint32_t ao = baseA + (uint32_t)(dy * XROWP * PIXB + h * 32);
                #pragma unroll
                for (int j = 0; j < 6; j++)
                    ldsm4(A + 4 * j, ao + j * PIXB);
                #pragma unroll
                for (int dx = 0; dx < 3; dx++) {
                    const uint32_t bo = baseB
                        + (uint32_t)((dy * 3 + dx) * (32 * WROWB) + h * 32);
                    ldsm4(B,     bo);
                    ldsm4(B + 4, bo + 16 * WROWB);
                    #pragma unroll
                    for (int f = 0; f < 4; f++)
                        #pragma unroll
                        for (int nb = 0; nb < 4; nb++)
                            mma4(d[f][nb], A + 4 * (f + dx), B + 2 * nb);
                }
            }
        }

        // ---- epilogue: per-warp smem transpose -> coalesced STG.128 ----
        const int R1 = R0 + r0;
        const int R2c = (R1 + 8 < H_OUT) ? (R1 + 8) : (H_OUT - 1);
        const float* act1 = g_active + (n * NBH + R1 / 14) * NBW;
        const float* act2 = g_active + (n * NBH + R2c / 14) * NBW;

        #pragma unroll 1
        for (int f = 0; f < 4; f++) {
            const int C = C0 + cw + f;
            const int cb = (C < W_OUT ? C : W_OUT - 1) / 14;
            const float fg1 = act1[cb];
            const float fg2 = act2[cb];
            // STS: [row16][160B row: co32 fp32 + pad]; conflict-free (stride 160)
            #pragma unroll
            for (int nb = 0; nb < 4; nb++) {
                float2 v0, v1;
                v0.x = (d[f][nb][0] + bv[nb].x) * fg1;
                v0.y = (d[f][nb][1] + bv[nb].y) * fg1;
                v1.x = (d[f][nb][2] + bv[nb].x) * fg2;
                v1.y = (d[f][nb][3] + bv[nb].y) * fg2;
                uint32_t a0 = eb + (uint32_t)(r0 * 160 + (nb * 8 + n2) * 4);
                sts64(a0, *reinterpret_cast<uint64_t*>(&v0));
                sts64(a0 + 8 * 160, *reinterpret_cast<uint64_t*>(&v1));
            }
            __syncwarp();
            // LDS.128 + STG.128: 4 rows per op, fully coalesced
            if (C < W_OUT) {
                const int q = lid & 7;
                #pragma unroll
                for (int i = 0; i < 4; i++) {
                    int row = i * 4 + (lid >> 3);
                    float4 v;
                    lds128(eb + (uint32_t)(row * 160 + q * 16), v);
                    int R = R0 + row;
                    if (R < H_OUT) {
                        *(float4*)(out + (((size_t)n * H_OUT + R) * W_OUT + C) * 32
                                   + q * 4) = v;
                    }
                }
            }
            __syncwarp();
        }
    }
}

// ---------------------------------------------------------------------------
extern "C" void kernel_launch(void* const* d_in, const int* in_sizes, int n_in,
                              void* d_out, int out_size)
{
    const float* x    = (const float*)d_in[0];
    const float* mask = (const float*)d_in[1];
    const float* kern = (const float*)d_in[2];
    const float* bias = (const float*)d_in[3];
    float* out = (float*)d_out;
    (void)in_sizes; (void)n_in; (void)out_size;

    cudaFuncSetAttribute(conv_mma_kernel,
                         cudaFuncAttributeMaxDynamicSharedMemorySize, SMEM_BYTES);

    mask_kernel<<<N_IMG * NBH * NBW, 256>>>(mask);
    conv_mma_kernel<<<GRID_CONV, THREADS, SMEM_BYTES>>>(x, kern, bias, out);
}

// round 13
// speedup vs baseline: 1.0046x; 1.0046x over previous
#include <cuda_runtime.h>
#include <cuda_fp16.h>
#include <cstdint>

// out[n,R,C,co] = active[n,R/14,C/14] * (bias[co] + sum_{dy,dx,ci} x[n,R+dy,C+dx,ci]*k[dy,dx,ci,co])
// valid 3x3 conv 506x506 -> 504x504, gated per 14x14 tile by mask-block max > 0.5
//
// mma.sync fp16 single-product. Persistent CTAs, 2 CTAs/SM, 256 thr, tile 16x32.
// This round: coalesced staging LDG (oct-inner: 8 lanes = one pixel's 128B) and
// smem-transposed epilogue (conflict-free, fully coalesced STG.128).

#define N_IMG 8
#define H_IN  506
#define W_IN  506
#define H_OUT 504
#define W_OUT 504
#define NBH   36
#define NBW   36

#define RT_CNT 32                     // 16-row tiles (rows 496.. guarded)
#define CT_CNT 16                     // 32-col tiles (cols 480.. guarded)
#define TPI    (RT_CNT * CT_CNT)      // 512
#define N_TILES (N_IMG * TPI)         // 4096
#define GRID_CONV 296

#define THREADS 256

#define XROWP 35                      // pixel-column pitch (odd 16B pitch)
#define PIXB  80                      // 64B fp16 ci0-31 + 16 pad
#define XS_BYTES (18 * XROWP * PIXB)  // 50400
#define WROWB 80                      // 64B fp16 ci + 16 pad
#define WS_BYTES (9 * 32 * WROWB)     // 23040
#define EPIB  2560                    // per-warp epilogue buffer: 16 rows x 160B
#define SMEM_BYTES (XS_BYTES + WS_BYTES + 8 * EPIB)   // 93920 -> 2 CTAs/SM

__device__ float g_active[N_IMG * NBH * NBW];

// ------------------------- helpers ------------------------------------------
__device__ __forceinline__ uint32_t smem_u32(const void* p) {
    uint32_t a;
    asm("{ .reg .u64 t; cvta.to.shared.u64 t, %1; cvt.u32.u64 %0, t; }"
        : "=r"(a) : "l"(p));
    return a;
}
__device__ __forceinline__ void sts64(uint32_t a, uint64_t v) {
    asm volatile("st.shared.b64 [%0], %1;" :: "r"(a), "l"(v) : "memory");
}
__device__ __forceinline__ void lds128(uint32_t a, float4& v) {
    asm volatile("ld.shared.v4.f32 {%0,%1,%2,%3}, [%4];"
                 : "=f"(v.x), "=f"(v.y), "=f"(v.z), "=f"(v.w) : "r"(a));
}
__device__ __forceinline__ void ldsm4(uint32_t* r, uint32_t addr) {
    asm volatile("ldmatrix.sync.aligned.m8n8.x4.shared.b16 {%0,%1,%2,%3}, [%4];"
                 : "=r"(r[0]), "=r"(r[1]), "=r"(r[2]), "=r"(r[3]) : "r"(addr));
}
__device__ __forceinline__ void mma4(float* d, const uint32_t* a, const uint32_t* b) {
    asm volatile(
        "mma.sync.aligned.m16n8k16.row.col.f32.f16.f16.f32 "
        "{%0,%1,%2,%3},{%4,%5,%6,%7},{%8,%9},{%0,%1,%2,%3};"
        : "+f"(d[0]), "+f"(d[1]), "+f"(d[2]), "+f"(d[3])
        : "r"(a[0]), "r"(a[1]), "r"(a[2]), "r"(a[3]), "r"(b[0]), "r"(b[1]));
}

// ---------------- kernel 1: mask block max -> active flag -------------------
__global__ void __launch_bounds__(256) mask_kernel(const float* __restrict__ mask) {
    __shared__ float red[256];
    int b = blockIdx.x;
    int n   = b / (NBH * NBW);
    int rem = b % (NBH * NBW);
    int bi = rem / NBW, bj = rem % NBW;
    int tid = threadIdx.x;
    int rr = tid >> 4, cc = tid & 15;
    red[tid] = mask[(n * H_IN + bi * 14 + rr) * W_IN + bj * 14 + cc];
    __syncthreads();
    #pragma unroll
    for (int s = 128; s > 0; s >>= 1) {
        if (tid < s) red[tid] = fmaxf(red[tid], red[tid + s]);
        __syncthreads();
    }
    if (tid == 0) g_active[b] = (red[0] > 0.5f) ? 1.0f : 0.0f;
}

// ---------------- kernel 2: persistent conv via mma.sync fp16 ---------------
__global__ void __launch_bounds__(THREADS, 2) conv_mma_kernel(
    const float* __restrict__ x,
    const float* __restrict__ kern,
    const float* __restrict__ bias,
    float* __restrict__ out)
{
    extern __shared__ char smem[];
    const uint32_t xs = smem_u32(smem);
    const uint32_t ws = xs + XS_BYTES;
    const uint32_t es = ws + WS_BYTES;
    const int tid = threadIdx.x;
    const int wid = tid >> 5;
    const int lid = tid & 31;

    // ---- stage weights once: kern[tap][ci][co] -> ws[tap][co][ci fp16] ----
    for (int j = tid; j < 2304; j += THREADS) {
        int ciq = j & 7;
        int co  = (j >> 3) & 31;
        int tap = j >> 8;
        int ci  = ciq * 4;
        const float* kp = kern + (tap * 32 + ci) * 32 + co;
        __half2 p0 = __floats2half2_rn(kp[0],  kp[32]);
        __half2 p1 = __floats2half2_rn(kp[64], kp[96]);
        uint64_t v = (uint64_t)(*reinterpret_cast<uint32_t*>(&p0))
                   | ((uint64_t)(*reinterpret_cast<uint32_t*>(&p1)) << 32);
        sts64(ws + (uint32_t)((tap * 32 + co) * WROWB + ciq * 8), v);
    }

    // per-lane ldmatrix base addresses
    const int cw = wid * 4;
    const int irl = (lid & 7) + 8 * ((lid >> 3) & 1);
    const uint32_t baseA = xs + (uint32_t)
        ((irl * XROWP + cw) * PIXB + ((lid >> 4) & 1) * 16);
    const uint32_t baseB = ws + (uint32_t)
        ((((lid & 7) + ((lid >> 4) << 3)) * WROWB) + ((lid >> 3) & 1) * 16);

    // epilogue lane constants
    const int n2 = (lid & 3) * 2;
    const int r0 = lid >> 2;
    const uint32_t eb = es + (uint32_t)(wid * EPIB);
    float2 bv[4];
    #pragma unroll
    for (int nb = 0; nb < 4; nb++)
        bv[nb] = *(const float2*)(bias + nb * 8 + n2);

    for (int t = blockIdx.x; t < N_TILES; t += GRID_CONV) {
        const int n   = t / TPI;
        const int rem = t % TPI;
        const int R0 = (rem >> 4) * 16;
        const int C0 = (rem & 15) * 32;

        __syncthreads();   // previous iteration's readers done before overwrite

        // ---- stage x: 18 rows x 34 cols x 32 ci fp16 (oct-INNER: coalesced) ----
        for (int j = tid; j < 18 * 34 * 8; j += THREADS) {
            int oct = j & 7;                   // 4-ci group (8 lanes = 128B pixel)
            int p   = j >> 3;
            int ir = p / 34, ic = p - ir * 34;
            int gr = R0 + ir; if (gr > H_IN - 1) gr = H_IN - 1;
            int gc = C0 + ic; if (gc > W_IN - 1) gc = W_IN - 1;
            float4 v = *(const float4*)
                (x + (((size_t)n * H_IN + gr) * W_IN + gc) * 32 + oct * 4);
            __half2 h0 = __floats2half2_rn(v.x, v.y);
            __half2 h1 = __floats2half2_rn(v.z, v.w);
            uint64_t pk = (uint64_t)(*reinterpret_cast<uint32_t*>(&h0))
                        | ((uint64_t)(*reinterpret_cast<uint32_t*>(&h1)) << 32);
            sts64(xs + (uint32_t)((ir * XROWP + ic) * PIXB + oct * 8), pk);
        }
        __syncthreads();

        // ---- main loop: dy x h, A-frags shared across dx, single product ----
        float d[4][4][4];
        #pragma unroll
        for (int f = 0; f < 4; f++)
            #pragma unroll
            for (int nb = 0; nb < 4; nb++)
                #pragma unroll
                for (int e = 0; e < 4; e++) d[f][nb][e] = 0.0f;

        #pragma unroll 1
        for (int dy = 0; dy < 3; dy++) {
            #pragma unroll
            for (int h = 0; h < 2; h++) {
                uint32_t A[24], B[8];
                const uint32_t ao = baseA + (uint32_t)(dy * XROWP * PIXB + h * 32);
                #pragma unroll
                for (int j = 0; j < 6; j++)
                    ldsm4(A + 4 * j, ao + j * PIXB);
                #pragma unroll
                for (int dx = 0; dx < 3; dx++) {
                    const uint32_t bo = baseB
                        + (uint32_t)((dy * 3 + dx) * (32 * WROWB) + h * 32);
                    ldsm4(B,     bo);
                    ldsm4(B + 4, bo + 16 * WROWB);
                    #pragma unroll
                    for (int f = 0; f < 4; f++)
                        #pragma unroll
                        for (int nb = 0; nb < 4; nb++)
                            mma4(d[f][nb], A + 4 * (f + dx), B + 2 * nb);
                }
            }
        }

        // ---- epilogue: per-warp smem transpose -> coalesced STG.128 ----
        const int R1 = R0 + r0;
        const int R2c = (R1 + 8 < H_OUT) ? (R1 + 8) : (H_OUT - 1);
        const float* act1 = g_active + (n * NBH + R1 / 14) * NBW;
        const float* act2 = g_active + (n * NBH + R2c / 14) * NBW;

        #pragma unroll 1
        for (int f = 0; f < 4; f++) {
            const int C = C0 + cw + f;
            const int cb = (C < W_OUT ? C : W_OUT - 1) / 14;
            const float fg1 = act1[cb];
            const float fg2 = act2[cb];
            // STS: [row16][160B row: co32 fp32 + pad]; conflict-free (stride 160)
            #pragma unroll
            for (int nb = 0; nb < 4; nb++) {
                float2 v0, v1;
                v0.x = (d[f][nb][0] + bv[nb].x) * fg1;
                v0.y = (d[f][nb][1] + bv[nb].y) * fg1;
                v1.x = (d[f][nb][2] + bv[nb].x) * fg2;
                v1.y = (d[f][nb][3] + bv[nb].y) * fg2;
                uint32_t a0 = eb + (uint32_t)(r0 * 160 + (nb * 8 + n2) * 4);
                sts64(a0, *reinterpret_cast<uint64_t*>(&v0));
                sts64(a0 + 8 * 160, *reinterpret_cast<uint64_t*>(&v1));
            }
            __syncwarp();
            // LDS.128 + STG.128: 4 rows per op, fully coalesced
            if (C < W_OUT) {
                const int q = lid & 7;
                #pragma unroll
                for (int i = 0; i < 4; i++) {
                    int row = i * 4 + (lid >> 3);
                    float4 v;
                    lds128(eb + (uint32_t)(row * 160 + q * 16), v);
                    int R = R0 + row;
                    if (R < H_OUT) {
                        *(float4*)(out + (((size_t)n * H_OUT + R) * W_OUT + C) * 32
                                   + q * 4) = v;
                    }
                }
            }
            __syncwarp();
        }
    }
}

// ---------------------------------------------------------------------------
extern "C" void kernel_launch(void* const* d_in, const int* in_sizes, int n_in,
                              void* d_out, int out_size)
{
    const float* x    = (const float*)d_in[0];
    const float* mask = (const float*)d_in[1];
    const float* kern = (const float*)d_in[2];
    const float* bias = (const float*)d_in[3];
    float* out = (float*)d_out;
    (void)in_sizes; (void)n_in; (void)out_size;

    cudaFuncSetAttribute(conv_mma_kernel,
                         cudaFuncAttributeMaxDynamicSharedMemorySize, SMEM_BYTES);

    mask_kernel<<<N_IMG * NBH * NBW, 256>>>(mask);
    conv_mma_kernel<<<GRID_CONV, THREADS, SMEM_BYTES>>>(x, kern, bias, out);
}

// round 14
// speedup vs baseline: 1.2126x; 1.2070x over previous
#include <cuda_runtime.h>
#include <cuda_fp16.h>
#include <cstdint>

// out[n,R,C,co] = active[n,R/14,C/14] * (bias[co] + sum_{dy,dx,ci} x[n,R+dy,C+dx,ci]*k[dy,dx,ci,co])
// valid 3x3 conv 506x506 -> 504x504, gated per 14x14 tile by mask-block max > 0.5
//
// fp16 single-product mma.sync. Pipeline:
//   prep_kernel: x fp32 -> fp16 once (device buffer)
//   conv: persistent 148 CTAs, 256 thr, double-buffered X staged via cp.async
//   (prefetch tile k+1 during tile k's MMAs). Mainloop/epilogue = r11 (201us champion).

#define N_IMG 8
#define H_IN  506
#define W_IN  506
#define H_OUT 504
#define W_OUT 504
#define NBH   36
#define NBW   36

#define RT_CNT 32                     // 16-row tiles (rows 496.. guarded)
#define CT_CNT 16                     // 32-col tiles (cols 480.. guarded)
#define TPI    (RT_CNT * CT_CNT)      // 512
#define N_TILES (N_IMG * TPI)         // 4096
#define GRID_CONV 148

#define THREADS 256

#define XROWP 35                      // pixel-column pitch (odd 16B pitch)
#define PIXB  80                      // 64B fp16 ci0-31 + 16 pad
#define XBUF  (18 * XROWP * PIXB)     // 50400 per buffer
#define WROWB 80                      // 64B fp16 ci + 16 pad
#define WS_BYTES (9 * 32 * WROWB)     // 23040
#define SMEM_BYTES (2 * XBUF + WS_BYTES)   // 123840 -> 1 CTA/SM

#define XH_ELEMS ((size_t)N_IMG * H_IN * W_IN * 32)   // 65,545,216

__device__ float g_active[N_IMG * NBH * NBW];
__device__ __half g_xh[XH_ELEMS];     // pre-converted fp16 x (131 MB)

// ------------------------- helpers ------------------------------------------
__device__ __forceinline__ uint32_t smem_u32(const void* p) {
    uint32_t a;
    asm("{ .reg .u64 t; cvta.to.shared.u64 t, %1; cvt.u32.u64 %0, t; }"
        : "=r"(a) : "l"(p));
    return a;
}
__device__ __forceinline__ void sts64(uint32_t a, uint64_t v) {
    asm volatile("st.shared.b64 [%0], %1;" :: "r"(a), "l"(v) : "memory");
}
__device__ __forceinline__ void cp_async16(uint32_t dst, const void* src) {
    asm volatile("cp.async.cg.shared.global [%0], [%1], 16;"
                 :: "r"(dst), "l"(src) : "memory");
}
__device__ __forceinline__ void cp_commit() {
    asm volatile("cp.async.commit_group;" ::: "memory");
}
__device__ __forceinline__ void cp_wait0() {
    asm volatile("cp.async.wait_group 0;" ::: "memory");
}
__device__ __forceinline__ void ldsm4(uint32_t* r, uint32_t addr) {
    asm volatile("ldmatrix.sync.aligned.m8n8.x4.shared.b16 {%0,%1,%2,%3}, [%4];"
                 : "=r"(r[0]), "=r"(r[1]), "=r"(r[2]), "=r"(r[3]) : "r"(addr));
}
__device__ __forceinline__ void mma4(float* d, const uint32_t* a, const uint32_t* b) {
    asm volatile(
        "mma.sync.aligned.m16n8k16.row.col.f32.f16.f16.f32 "
        "{%0,%1,%2,%3},{%4,%5,%6,%7},{%8,%9},{%0,%1,%2,%3};"
        : "+f"(d[0]), "+f"(d[1]), "+f"(d[2]), "+f"(d[3])
        : "r"(a[0]), "r"(a[1]), "r"(a[2]), "r"(a[3]), "r"(b[0]), "r"(b[1]));
}

// ---------------- kernel 0: convert x to fp16 --------------------------------
__global__ void __launch_bounds__(256) prep_kernel(const float* __restrict__ x) {
    size_t i = ((size_t)blockIdx.x * 256 + threadIdx.x) * 8;
    if (i < XH_ELEMS) {
        float4 a = *(const float4*)(x + i);
        float4 b = *(const float4*)(x + i + 4);
        __half2 h0 = __floats2half2_rn(a.x, a.y);
        __half2 h1 = __floats2half2_rn(a.z, a.w);
        __half2 h2 = __floats2half2_rn(b.x, b.y);
        __half2 h3 = __floats2half2_rn(b.z, b.w);
        uint4 v;
        v.x = *reinterpret_cast<uint32_t*>(&h0);
        v.y = *reinterpret_cast<uint32_t*>(&h1);
        v.z = *reinterpret_cast<uint32_t*>(&h2);
        v.w = *reinterpret_cast<uint32_t*>(&h3);
        *reinterpret_cast<uint4*>(&g_xh[i]) = v;
    }
}

// ---------------- kernel 1: mask block max -> active flag -------------------
__global__ void __launch_bounds__(256) mask_kernel(const float* __restrict__ mask) {
    __shared__ float red[256];
    int b = blockIdx.x;
    int n   = b / (NBH * NBW);
    int rem = b % (NBH * NBW);
    int bi = rem / NBW, bj = rem % NBW;
    int tid = threadIdx.x;
    int rr = tid >> 4, cc = tid & 15;
    red[tid] = mask[(n * H_IN + bi * 14 + rr) * W_IN + bj * 14 + cc];
    __syncthreads();
    #pragma unroll
    for (int s = 128; s > 0; s >>= 1) {
        if (tid < s) red[tid] = fmaxf(red[tid], red[tid + s]);
        __syncthreads();
    }
    if (tid == 0) g_active[b] = (red[0] > 0.5f) ? 1.0f : 0.0f;
}

// ---------------- cp.async prefetch of one tile's x --------------------------
__device__ __forceinline__ void issue_tile(uint32_t dstbase, int n, int R0, int C0,
                                           int tid) {
    for (int j = tid; j < 18 * 34 * 4; j += THREADS) {
        int chunk = j & 3;                // 16B chunk within the 64B pixel
        int p = j >> 2;
        int ir = p / 34, ic = p - ir * 34;
        int gr = R0 + ir; if (gr > H_IN - 1) gr = H_IN - 1;
        int gc = C0 + ic; if (gc > W_IN - 1) gc = W_IN - 1;
        const __half* src = g_xh + (((size_t)n * H_IN + gr) * W_IN + gc) * 32
                          + chunk * 8;
        cp_async16(dstbase + (uint32_t)((ir * XROWP + ic) * PIXB + chunk * 16), src);
    }
}

// ---------------- kernel 2: persistent conv, cp.async pipelined -------------
__global__ void __launch_bounds__(THREADS, 1) conv_mma_kernel(
    const float* __restrict__ kern,
    const float* __restrict__ bias,
    float* __restrict__ out)
{
    extern __shared__ char smem[];
    const uint32_t xs0 = smem_u32(smem);
    const uint32_t ws  = xs0 + 2 * XBUF;
    const int tid = threadIdx.x;
    const int wid = tid >> 5;
    const int lid = tid & 31;
    const int bid = blockIdx.x;

    // ---- stage weights once: kern[tap][ci][co] -> ws[tap][co][ci fp16] ----
    for (int j = tid; j < 2304; j += THREADS) {
        int ciq = j & 7;
        int co  = (j >> 3) & 31;
        int tap = j >> 8;
        int ci  = ciq * 4;
        const float* kp = kern + (tap * 32 + ci) * 32 + co;
        __half2 p0 = __floats2half2_rn(kp[0],  kp[32]);
        __half2 p1 = __floats2half2_rn(kp[64], kp[96]);
        uint64_t v = (uint64_t)(*reinterpret_cast<uint32_t*>(&p0))
                   | ((uint64_t)(*reinterpret_cast<uint32_t*>(&p1)) << 32);
        sts64(ws + (uint32_t)((tap * 32 + co) * WROWB + ciq * 8), v);
    }

    // per-lane ldmatrix base addresses (identical to the 201us kernel)
    const int cw = wid * 4;
    const int irl = (lid & 7) + 8 * ((lid >> 3) & 1);
    const uint32_t baseAoff = (uint32_t)
        ((irl * XROWP + cw) * PIXB + ((lid >> 4) & 1) * 16);
    const uint32_t baseB = ws + (uint32_t)
        ((((lid & 7) + ((lid >> 4) << 3)) * WROWB) + ((lid >> 3) & 1) * 16);

    const int n2 = (lid & 3) * 2;
    float2 bv[4];
    #pragma unroll
    for (int nb = 0; nb < 4; nb++)
        bv[nb] = *(const float2*)(bias + nb * 8 + n2);

    const int nT = (N_TILES - bid + GRID_CONV - 1) / GRID_CONV;

    // prologue: prefetch tile 0 into buffer 0
    {
        int t = bid;
        int n = t / TPI, rem = t % TPI;
        issue_tile(xs0, n, (rem >> 4) * 16, (rem & 15) * 32, tid);
        cp_commit();
    }

    for (int k = 0; k < nT; k++) {
        cp_wait0();                    // buffer k&1 data arrived (this thread's)
        __syncthreads();               // all threads' data visible; prev buf free

        const int t   = bid + k * GRID_CONV;
        const int n   = t / TPI;
        const int rem = t % TPI;
        const int R0 = (rem >> 4) * 16;
        const int C0 = (rem & 15) * 32;
        const uint32_t baseA = xs0 + (uint32_t)((k & 1) * XBUF) + baseAoff;

        // prefetch next tile into the other buffer (fully async)
        if (k + 1 < nT) {
            int t1 = bid + (k + 1) * GRID_CONV;
            int n1 = t1 / TPI, rem1 = t1 % TPI;
            issue_tile(xs0 + (uint32_t)(((k + 1) & 1) * XBUF), n1,
                       (rem1 >> 4) * 16, (rem1 & 15) * 32, tid);
            cp_commit();
        }

        // ---- main loop: dy x h, A-frags shared across dx, single product ----
        float d[4][4][4];
        #pragma unroll
        for (int f = 0; f < 4; f++)
            #pragma unroll
            for (int nb = 0; nb < 4; nb++)
                #pragma unroll
                for (int e = 0; e < 4; e++) d[f][nb][e] = 0.0f;

        #pragma unroll 1
        for (int dy = 0; dy < 3; dy++) {
            #pragma unroll
            for (int h = 0; h < 2; h++) {
                uint32_t A[24], B[8];
                const uint32_t ao = baseA + (uint32_t)(dy * XROWP * PIXB + h * 32);
                #pragma unroll
                for (int j = 0; j < 6; j++)
                    ldsm4(A + 4 * j, ao + j * PIXB);
                #pragma unroll
                for (int dx = 0; dx < 3; dx++) {
                    const uint32_t bo = baseB
                        + (uint32_t)((dy * 3 + dx) * (32 * WROWB) + h * 32);
                    ldsm4(B,     bo);
                    ldsm4(B + 4, bo + 16 * WROWB);
                    #pragma unroll
                    for (int f = 0; f < 4; f++)
                        #pragma unroll
                        for (int nb = 0; nb < 4; nb++)
                            mma4(d[f][nb], A + 4 * (f + dx), B + 2 * nb);
                }
            }
        }

        // ---- epilogue (r11 scattered form) ----
        const int r0 = lid >> 2;
        const int R1 = R0 + r0;
        const int R2 = R1 + 8;
        const bool r2ok = (R2 < H_OUT);
        const int R2c = r2ok ? R2 : H_OUT - 1;
        const float* act1 = g_active + (n * NBH + R1 / 14) * NBW;
        const float* act2 = g_active + (n * NBH + R2c / 14) * NBW;

        #pragma unroll
        for (int f = 0; f < 4; f++) {
            const int C = C0 + cw + f;
            if (C < W_OUT) {
                const int cb = C / 14;
                float fg1 = act1[cb];
                float* o1 = out + (((size_t)n * H_OUT + R1) * W_OUT + C) * 32 + n2;
                #pragma unroll
                for (int nb = 0; nb < 4; nb++) {
                    float2 v;
                    v.x = (d[f][nb][0] + bv[nb].x) * fg1;
                    v.y = (d[f][nb][1] + bv[nb].y) * fg1;
                    *(float2*)(o1 + nb * 8) = v;
                }
                if (r2ok) {
                    float fg2 = act2[cb];
                    float* o2 = out + (((size_t)n * H_OUT + R2) * W_OUT + C) * 32 + n2;
                    #pragma unroll
                    for (int nb = 0; nb < 4; nb++) {
                        float2 v;
                        v.x = (d[f][nb][2] + bv[nb].x) * fg2;
                        v.y = (d[f][nb][3] + bv[nb].y) * fg2;
                        *(float2*)(o2 + nb * 8) = v;
                    }
                }
            }
        }
    }
}

// ---------------------------------------------------------------------------
extern "C" void kernel_launch(void* const* d_in, const int* in_sizes, int n_in,
                              void* d_out, int out_size)
{
    const float* x    = (const float*)d_in[0];
    const float* mask = (const float*)d_in[1];
    const float* kern = (const float*)d_in[2];
    const float* bias = (const float*)d_in[3];
    float* out = (float*)d_out;
    (void)in_sizes; (void)n_in; (void)out_size;

    cudaFuncSetAttribute(conv_mma_kernel,
                         cudaFuncAttributeMaxDynamicSharedMemorySize, SMEM_BYTES);

    prep_kernel<<<(int)((XH_ELEMS / 8 + 255) / 256), 256>>>(x);
    mask_kernel<<<N_IMG * NBH * NBW, 256>>>(mask);
    conv_mma_kernel<<<GRID_CONV, THREADS, SMEM_BYTES>>>(kern, bias, out);
}

// round 15
// speedup vs baseline: 1.2930x; 1.0663x over previous
#include <cuda_runtime.h>
#include <cuda_fp16.h>
#include <cstdint>

// out[n,R,C,co] = active[n,R/14,C/14] * (bias[co] + sum_{dy,dx,ci} x[n,R+dy,C+dx,ci]*k[dy,dx,ci,co])
// valid 3x3 conv 506x506 -> 504x504, gated per 14x14 tile by mask-block max > 0.5
//
// fp16 single-product mma.sync:
//   prep_kernel: x fp32 -> fp16 once (device buffer, DRAM-roofline ~52us)
//   conv: persistent, 2 CTAs/SM (16 warps/SM), tile 16x24, warp = 3 cols x 16 rows,
//   double-buffered X staged via cp.async (prefetch k+1 during k's MMAs).

#define N_IMG 8
#define H_IN  506
#define W_IN  506
#define H_OUT 504
#define W_OUT 504
#define NBH   36
#define NBW   36

#define RT_CNT 32                     // 16-row tiles (rows 496.. guarded)
#define CT_CNT 21                     // 24-col tiles: 21*24 = 504 exact
#define TPI    (RT_CNT * CT_CNT)      // 672
#define N_TILES (N_IMG * TPI)         // 5376
#define GRID_CONV 296

#define THREADS 256

#define XROWP 26                      // pixel-column pitch (24 + 2 halo)
#define PIXB  80                      // 64B fp16 ci0-31 + 16 pad (odd 16B pitch)
#define XBUF  (18 * XROWP * PIXB)     // 37440 per buffer
#define WROWB 80                      // 64B fp16 ci + 16 pad
#define WS_BYTES (9 * 32 * WROWB)     // 23040
#define SMEM_BYTES (2 * XBUF + WS_BYTES)   // 97920 -> 2 CTAs/SM

#define XH_ELEMS ((size_t)N_IMG * H_IN * W_IN * 32)   // 65,545,216

__device__ float g_active[N_IMG * NBH * NBW];
__device__ __half g_xh[XH_ELEMS];     // pre-converted fp16 x (131 MB)

// ------------------------- helpers ------------------------------------------
__device__ __forceinline__ uint32_t smem_u32(const void* p) {
    uint32_t a;
    asm("{ .reg .u64 t; cvta.to.shared.u64 t, %1; cvt.u32.u64 %0, t; }"
        : "=r"(a) : "l"(p));
    return a;
}
__device__ __forceinline__ void sts64(uint32_t a, uint64_t v) {
    asm volatile("st.shared.b64 [%0], %1;" :: "r"(a), "l"(v) : "memory");
}
__device__ __forceinline__ void cp_async16(uint32_t dst, const void* src) {
    asm volatile("cp.async.cg.shared.global [%0], [%1], 16;"
                 :: "r"(dst), "l"(src) : "memory");
}
__device__ __forceinline__ void cp_commit() {
    asm volatile("cp.async.commit_group;" ::: "memory");
}
__device__ __forceinline__ void cp_wait0() {
    asm volatile("cp.async.wait_group 0;" ::: "memory");
}
__device__ __forceinline__ void ldsm4(uint32_t* r, uint32_t addr) {
    asm volatile("ldmatrix.sync.aligned.m8n8.x4.shared.b16 {%0,%1,%2,%3}, [%4];"
                 : "=r"(r[0]), "=r"(r[1]), "=r"(r[2]), "=r"(r[3]) : "r"(addr));
}
__device__ __forceinline__ void mma4(float* d, const uint32_t* a, const uint32_t* b) {
    asm volatile(
        "mma.sync.aligned.m16n8k16.row.col.f32.f16.f16.f32 "
        "{%0,%1,%2,%3},{%4,%5,%6,%7},{%8,%9},{%0,%1,%2,%3};"
        : "+f"(d[0]), "+f"(d[1]), "+f"(d[2]), "+f"(d[3])
        : "r"(a[0]), "r"(a[1]), "r"(a[2]), "r"(a[3]), "r"(b[0]), "r"(b[1]));
}

// ---------------- kernel 0: convert x to fp16 --------------------------------
__global__ void __launch_bounds__(256) prep_kernel(const float* __restrict__ x) {
    size_t i = ((size_t)blockIdx.x * 256 + threadIdx.x) * 8;
    if (i < XH_ELEMS) {
        float4 a = *(const float4*)(x + i);
        float4 b = *(const float4*)(x + i + 4);
        __half2 h0 = __floats2half2_rn(a.x, a.y);
        __half2 h1 = __floats2half2_rn(a.z, a.w);
        __half2 h2 = __floats2half2_rn(b.x, b.y);
        __half2 h3 = __floats2half2_rn(b.z, b.w);
        uint4 v;
        v.x = *reinterpret_cast<uint32_t*>(&h0);
        v.y = *reinterpret_cast<uint32_t*>(&h1);
        v.z = *reinterpret_cast<uint32_t*>(&h2);
        v.w = *reinterpret_cast<uint32_t*>(&h3);
        *reinterpret_cast<uint4*>(&g_xh[i]) = v;
    }
}

// ---------------- kernel 1: mask block max -> active flag -------------------
__global__ void __launch_bounds__(256) mask_kernel(const float* __restrict__ mask) {
    __shared__ float red[256];
    int b = blockIdx.x;
    int n   = b / (NBH * NBW);
    int rem = b % (NBH * NBW);
    int bi = rem / NBW, bj = rem % NBW;
    int tid = threadIdx.x;
    int rr = tid >> 4, cc = tid & 15;
    red[tid] = mask[(n * H_IN + bi * 14 + rr) * W_IN + bj * 14 + cc];
    __syncthreads();
    #pragma unroll
    for (int s = 128; s > 0; s >>= 1) {
        if (tid < s) red[tid] = fmaxf(red[tid], red[tid + s]);
        __syncthreads();
    }
    if (tid == 0) g_active[b] = (red[0] > 0.5f) ? 1.0f : 0.0f;
}

// ---------------- cp.async prefetch of one tile's x --------------------------
__device__ __forceinline__ void issue_tile(uint32_t dstbase, int n, int R0, int C0,
                                           int tid) {
    for (int j = tid; j < 18 * 26 * 4; j += THREADS) {
        int chunk = j & 3;                // 16B chunk within the 64B pixel
        int p = j >> 2;
        int ir = p / 26, ic = p - ir * 26;
        int gr = R0 + ir; if (gr > H_IN - 1) gr = H_IN - 1;
        int gc = C0 + ic;                 // <= 480+25 = 505, in range
        const __half* src = g_xh + (((size_t)n * H_IN + gr) * W_IN + gc) * 32
                          + chunk * 8;
        cp_async16(dstbase + (uint32_t)((ir * XROWP + ic) * PIXB + chunk * 16), src);
    }
}

// ---------------- kernel 2: persistent conv, cp.async pipelined -------------
__global__ void __launch_bounds__(THREADS, 2) conv_mma_kernel(
    const float* __restrict__ kern,
    const float* __restrict__ bias,
    float* __restrict__ out)
{
    extern __shared__ char smem[];
    const uint32_t xs0 = smem_u32(smem);
    const uint32_t ws  = xs0 + 2 * XBUF;
    const int tid = threadIdx.x;
    const int wid = tid >> 5;
    const int lid = tid & 31;
    const int bid = blockIdx.x;

    // ---- stage weights once: kern[tap][ci][co] -> ws[tap][co][ci fp16] ----
    for (int j = tid; j < 2304; j += THREADS) {
        int ciq = j & 7;
        int co  = (j >> 3) & 31;
        int tap = j >> 8;
        int ci  = ciq * 4;
        const float* kp = kern + (tap * 32 + ci) * 32 + co;
        __half2 p0 = __floats2half2_rn(kp[0],  kp[32]);
        __half2 p1 = __floats2half2_rn(kp[64], kp[96]);
        uint64_t v = (uint64_t)(*reinterpret_cast<uint32_t*>(&p0))
                   | ((uint64_t)(*reinterpret_cast<uint32_t*>(&p1)) << 32);
        sts64(ws + (uint32_t)((tap * 32 + co) * WROWB + ciq * 8), v);
    }

    // per-lane ldmatrix base addresses; warp = 3 output cols (cw..cw+2)
    const int cw = wid * 3;
    const int irl = (lid & 7) + 8 * ((lid >> 3) & 1);
    const uint32_t baseAoff = (uint32_t)
        ((irl * XROWP + cw) * PIXB + ((lid >> 4) & 1) * 16);
    const uint32_t baseB = ws + (uint32_t)
        ((((lid & 7) + ((lid >> 4) << 3)) * WROWB) + ((lid >> 3) & 1) * 16);

    const int n2 = (lid & 3) * 2;
    float2 bv[4];
    #pragma unroll
    for (int nb = 0; nb < 4; nb++)
        bv[nb] = *(const float2*)(bias + nb * 8 + n2);

    const int nT = (N_TILES - bid + GRID_CONV - 1) / GRID_CONV;

    // prologue: prefetch tile 0 into buffer 0
    {
        int t = bid;
        int n = t / TPI, rem = t % TPI;
        issue_tile(xs0, n, (rem / CT_CNT) * 16, (rem % CT_CNT) * 24, tid);
        cp_commit();
    }

    for (int k = 0; k < nT; k++) {
        cp_wait0();                    // buffer k&1 data arrived (this thread's)
        __syncthreads();               // all threads' data visible; prev buf free

        const int t   = bid + k * GRID_CONV;
        const int n   = t / TPI;
        const int rem = t % TPI;
        const int R0 = (rem / CT_CNT) * 16;
        const int C0 = (rem % CT_CNT) * 24;
        const uint32_t baseA = xs0 + (uint32_t)((k & 1) * XBUF) + baseAoff;

        // prefetch next tile into the other buffer (fully async)
        if (k + 1 < nT) {
            int t1 = bid + (k + 1) * GRID_CONV;
            int n1 = t1 / TPI, rem1 = t1 % TPI;
            issue_tile(xs0 + (uint32_t)(((k + 1) & 1) * XBUF), n1,
                       (rem1 / CT_CNT) * 16, (rem1 % CT_CNT) * 24, tid);
            cp_commit();
        }

        // ---- main loop: dy x h, 5 A-frags shared across dx, single product ----
        float d[3][4][4];
        #pragma unroll
        for (int f = 0; f < 3; f++)
            #pragma unroll
            for (int nb = 0; nb < 4; nb++)
                #pragma unroll
                for (int e = 0; e < 4; e++) d[f][nb][e] = 0.0f;

        #pragma unroll 1
        for (int dy = 0; dy < 3; dy++) {
            #pragma unroll
            for (int h = 0; h < 2; h++) {
                uint32_t A[20], B[8];
                const uint32_t ao = baseA + (uint32_t)(dy * XROWP * PIXB + h * 32);
                #pragma unroll
                for (int j = 0; j < 5; j++)
                    ldsm4(A + 4 * j, ao + j * PIXB);
                #pragma unroll
                for (int dx = 0; dx < 3; dx++) {
                    const uint32_t bo = baseB
                        + (uint32_t)((dy * 3 + dx) * (32 * WROWB) + h * 32);
                    ldsm4(B,     bo);
                    ldsm4(B + 4, bo + 16 * WROWB);
                    #pragma unroll
                    for (int f = 0; f < 3; f++)
                        #pragma unroll
                        for (int nb = 0; nb < 4; nb++)
                            mma4(d[f][nb], A + 4 * (f + dx), B + 2 * nb);
                }
            }
        }

        // ---- epilogue (cols exact: 21*24 = 504; rows guarded) ----
        const int r0 = lid >> 2;
        const int R1 = R0 + r0;
        const int R2 = R1 + 8;
        const bool r2ok = (R2 < H_OUT);
        const int R2c = r2ok ? R2 : H_OUT - 1;
        const float* act1 = g_active + (n * NBH + R1 / 14) * NBW;
        const float* act2 = g_active + (n * NBH + R2c / 14) * NBW;

        #pragma unroll
        for (int f = 0; f < 3; f++) {
            const int C = C0 + cw + f;
            const int cb = C / 14;
            float fg1 = act1[cb];
            float* o1 = out + (((size_t)n * H_OUT + R1) * W_OUT + C) * 32 + n2;
            #pragma unroll
            for (int nb = 0; nb < 4; nb++) {
                float2 v;
                v.x = (d[f][nb][0] + bv[nb].x) * fg1;
                v.y = (d[f][nb][1] + bv[nb].y) * fg1;
                *(float2*)(o1 + nb * 8) = v;
            }
            if (r2ok) {
                float fg2 = act2[cb];
                float* o2 = out + (((size_t)n * H_OUT + R2) * W_OUT + C) * 32 + n2;
                #pragma unroll
                for (int nb = 0; nb < 4; nb++) {
                    float2 v;
                    v.x = (d[f][nb][2] + bv[nb].x) * fg2;
                    v.y = (d[f][nb][3] + bv[nb].y) * fg2;
                    *(float2*)(o2 + nb * 8) = v;
                }
            }
        }
    }
}

// ---------------------------------------------------------------------------
extern "C" void kernel_launch(void* const* d_in, const int* in_sizes, int n_in,
                              void* d_out, int out_size)
{
    const float* x    = (const float*)d_in[0];
    const float* mask = (const float*)d_in[1];
    const float* kern = (const float*)d_in[2];
    const float* bias = (const float*)d_in[3];
    float* out = (float*)d_out;
    (void)in_sizes; (void)n_in; (void)out_size;

    cudaFuncSetAttribute(conv_mma_kernel,
                         cudaFuncAttributeMaxDynamicSharedMemorySize, SMEM_BYTES);

    prep_kernel<<<(int)((XH_ELEMS / 8 + 255) / 256), 256>>>(x);
    mask_kernel<<<N_IMG * NBH * NBW, 256>>>(mask);
    conv_mma_kernel<<<GRID_CONV, THREADS, SMEM_BYTES>>>(kern, bias, out);
}